// round 3
// baseline (speedup 1.0000x reference)
#include <cuda_runtime.h>
#include <math.h>
#include <stdint.h>

// Problem constants (fixed by the dataset)
#define NN      4096
#define MM      2048
#define DVV     3
#define DCC     6
#define EE      (NN*DVV)      // 12288
#define BB      2048
#define NITER   5
#define THREADS 512
#define CN_PER_THREAD (MM/THREADS)   // 4

// SMEM: buf (E floats, msg_vn <-> msg_cn) | llr (N floats)
#define SMEM_BYTES (EE*4 + NN*4)     // 64 KB

// ---------------------------------------------------------------------------
// MUFU intrinsics
// ---------------------------------------------------------------------------
__device__ __forceinline__ float ex2a(float x){ float r; asm("ex2.approx.ftz.f32 %0, %1;" : "=f"(r) : "f"(x)); return r; }
__device__ __forceinline__ float lg2a(float x){ float r; asm("lg2.approx.ftz.f32 %0, %1;" : "=f"(r) : "f"(x)); return r; }

#define LOG2E_F 1.4426950408889634f
#define LN2_F   0.6931471805599453f
#define FMAX_F  27.631021115928547f   /* -ln(1e-12): emulates log(|t|+eps) floor      */
#define MAGMAX  16.635532f            /* 2*atanh(float(1-1e-7)): emulates CLIP        */

// f(x) = -ln(tanh(x/2)), x >= 0. Self-inverse. Branch-free two-regime approx.
// 2 MUFU + ~11 fixed-pipe ops.
__device__ __forceinline__ float f_op(float ax)
{
    // regime A (ax >= 1): f = 2*atanh(u), u = e^{-ax}
    float u  = ex2a(-ax * LOG2E_F);
    float u2 = u * u;
    float qL = fmaf(u2, 0.22222222f, 0.28571429f);   // 2/9, 2/7
    qL       = fmaf(u2, qL, 0.4f);                   // 2/5
    qL       = fmaf(u2, qL, 0.66666667f);            // 2/3
    qL       = fmaf(u2, qL, 2.0f);
    float fL = u * qL;

    // regime B (ax < 1): f = ln2*(1 - lg2(ax)) + ax^2/12 - 7ax^4/1440 + 62ax^6/181440
    float l  = lg2a(ax);
    float y  = ax * ax;
    float pS = fmaf(y, 3.4171076e-4f, -4.8611111e-3f);
    pS       = fmaf(y, pS, 8.3333333e-2f);
    float fS = fmaf(y, pS, fmaf(l, -LN2_F, LN2_F));

    return (ax >= 1.0f) ? fL : fS;
}

// ---------------------------------------------------------------------------
// Persistent scratch (static globals: no runtime allocation)
// ---------------------------------------------------------------------------
__device__ int   g_cnt[MM];
__device__ int   g_tmp[EE];        // g_tmp[m*6+slot] = edge id (atomic order)
__device__ uint4 g_cnp[MM * 3];    // per CN: [8 x u16 byte-offsets][8 x f32 weights]

// ---------------------------------------------------------------------------
// Prep kernels (deterministic after the sort)
// ---------------------------------------------------------------------------
__global__ void prep_zero()
{
    int i = blockIdx.x * blockDim.x + threadIdx.x;
    if (i < MM) g_cnt[i] = 0;
}

__global__ void prep_fill(const int* __restrict__ cn_idx)
{
    int e = blockIdx.x * blockDim.x + threadIdx.x;
    if (e < EE) {
        int m = cn_idx[e];
        int p = atomicAdd(&g_cnt[m], 1);
        g_tmp[m * DCC + p] = e;
    }
}

__global__ void prep_pack(const float* __restrict__ w)
{
    int m = blockIdx.x * blockDim.x + threadIdx.x;
    if (m >= MM) return;
    int a[DCC];
#pragma unroll
    for (int j = 0; j < DCC; j++) a[j] = g_tmp[m * DCC + j];
    // sort ascending -> deterministic edge order matching jax scatter-add
#pragma unroll
    for (int i = 0; i < DCC - 1; i++)
#pragma unroll
        for (int j = 0; j < DCC - 1 - i; j++)
            if (a[j] > a[j + 1]) { int t = a[j]; a[j] = a[j + 1]; a[j + 1] = t; }

    uint4 iw;   // 8 x u16 pre-scaled byte offsets (e*4), slots 6,7 = 0
    iw.x = (unsigned)(a[0] * 4) | ((unsigned)(a[1] * 4) << 16);
    iw.y = (unsigned)(a[2] * 4) | ((unsigned)(a[3] * 4) << 16);
    iw.z = (unsigned)(a[4] * 4) | ((unsigned)(a[5] * 4) << 16);
    iw.w = 0;
    g_cnp[m * 3 + 0] = iw;

    float4 w0, w1;
    w0.x = w[a[0]]; w0.y = w[a[1]]; w0.z = w[a[2]]; w0.w = w[a[3]];
    w1.x = w[a[4]]; w1.y = w[a[5]]; w1.z = 0.0f;   w1.w = 0.0f;
    g_cnp[m * 3 + 1] = *reinterpret_cast<uint4*>(&w0);
    g_cnp[m * 3 + 2] = *reinterpret_cast<uint4*>(&w1);
}

// ---------------------------------------------------------------------------
// Main BP kernel: one CTA per batch row, all state in SMEM
// ---------------------------------------------------------------------------
__global__ __launch_bounds__(THREADS, 2)
void bp_kernel(const float* __restrict__ noise_r,
               float* __restrict__ out)
{
    extern __shared__ unsigned char smem_raw[];
    float* buf = reinterpret_cast<float*>(smem_raw);   // E floats
    float* llr = buf + EE;                             // N floats

    const int row = blockIdx.x;
    const int tid = threadIdx.x;
    const float* nr = noise_r + (size_t)row * NN;

    const float NO_F = 0.3981071705534972f;            // 10^-0.4
    const float NSTD = 0.44615420f;                    // sqrtf(no/2) in f32

    // llr init + msg_vn init
    for (int v = tid; v < NN; v += THREADS) {
        float y = 1.0f + NSTD * nr[v];
        float l = (4.0f * y) / NO_F;
        llr[v] = l;
        buf[3 * v + 0] = l;
        buf[3 * v + 1] = l;
        buf[3 * v + 2] = l;
    }
    __syncthreads();

    for (int it = 0; it < NITER; ++it) {
        // ---- check-node pass (tanh/log fused in, registers only) ----
#pragma unroll
        for (int k = 0; k < CN_PER_THREAD; ++k) {
            const int m = tid + k * THREADS;
            const uint4 iw = __ldg(&g_cnp[m * 3 + 0]);
            const uint4 wa = __ldg(&g_cnp[m * 3 + 1]);
            const uint4 wb = __ldg(&g_cnp[m * 3 + 2]);

            unsigned off[6];
            off[0] = iw.x & 0xFFFFu;  off[1] = iw.x >> 16;
            off[2] = iw.y & 0xFFFFu;  off[3] = iw.y >> 16;
            off[4] = iw.z & 0xFFFFu;  off[5] = iw.z >> 16;
            float wgt[6];
            wgt[0] = __uint_as_float(wa.x); wgt[1] = __uint_as_float(wa.y);
            wgt[2] = __uint_as_float(wa.z); wgt[3] = __uint_as_float(wa.w);
            wgt[4] = __uint_as_float(wb.x); wgt[5] = __uint_as_float(wb.y);

            float    fv[6];
            unsigned sb[6];
            float    S    = 0.0f;
            unsigned sxor = 0u;
#pragma unroll
            for (int j = 0; j < 6; ++j) {
                float msg = *reinterpret_cast<const float*>(smem_raw + off[j]);
                float x   = msg * wgt[j];
                sb[j]     = __float_as_uint(x) & 0x80000000u;
                float fj  = fminf(f_op(fabsf(x)), FMAX_F);  // = -log(|tanh(x/2)|+eps)
                fv[j]     = fj;
                S        += fj;           // ascending edge order (matches ref)
                sxor     ^= sb[j];
            }
#pragma unroll
            for (int j = 0; j < 6; ++j) {
                float el  = fmaxf(S - fv[j], 0.0f);
                float mag = fminf(f_op(el), MAGMAX);        // = 2*atanh(clip(exp(-el)))
                unsigned bits = __float_as_uint(mag) | (sxor ^ sb[j]);
                *reinterpret_cast<float*>(smem_raw + off[j]) = __uint_as_float(bits);
            }
        }
        __syncthreads();

        // ---- variable-node pass: the 3 edges of VN v are contiguous ----
        const bool last = (it == NITER - 1);
        for (int v = tid; v < NN; v += THREADS) {
            float m0 = buf[3 * v + 0];
            float m1 = buf[3 * v + 1];
            float m2 = buf[3 * v + 2];
            float s  = (m0 + m1) + m2;      // ascending edge order
            float lt = llr[v] + s;
            if (last) {
                out[(size_t)row * NN + v] = lt;
            } else {
                buf[3 * v + 0] = lt - m0;
                buf[3 * v + 1] = lt - m1;
                buf[3 * v + 2] = lt - m2;
            }
        }
        __syncthreads();
    }
}

// ---------------------------------------------------------------------------
// Launch
// ---------------------------------------------------------------------------
extern "C" void kernel_launch(void* const* d_in, const int* in_sizes, int n_in,
                              void* d_out, int out_size)
{
    const float* noise_r = (const float*)d_in[0];
    // d_in[1] = noise_i (unused by the reference)
    const float* weights = (const float*)d_in[2];
    // d_in[3] = vn_idx (structural: e/3)
    const int*   cn_idx  = (const int*)d_in[4];
    float* out = (float*)d_out;

    (void)in_sizes; (void)n_in; (void)out_size;

    cudaFuncSetAttribute(bp_kernel, cudaFuncAttributeMaxDynamicSharedMemorySize, SMEM_BYTES);

    prep_zero<<<(MM + 255) / 256, 256>>>();
    prep_fill<<<(EE + 255) / 256, 256>>>(cn_idx);
    prep_pack<<<(MM + 255) / 256, 256>>>(weights);

    bp_kernel<<<BB, THREADS, SMEM_BYTES>>>(noise_r, out);
}